// round 16
// baseline (speedup 1.0000x reference)
#include <cuda_runtime.h>
#include <cstdint>

#define SIZE   128
#define EPSF   1e-6f
#define BW     4            // final operator half bandwidth
#define TAPS   9            // 2*BW+1
#define CW     12           // padded Lb coeff row width
#define SBW    5            // single-sweep inverse half-width
#define GW     11           // 2*SBW+1
#define HA1    10           // A1/A2 half-width (exact)
#define WA1    21
#define HC     12           // chain / E half-width (cap, validated)
#define WC     25

// ---------------------------------------------------------------------------
// Globals
// ---------------------------------------------------------------------------
// chains 0..3 = X chains (W = C0*C1*C2*C3), 4..5 = Y chains (L = C5*C4)
__device__ float g_cb[6][SIZE * WC];
__device__ float g_Lb[SIZE * CW];          // row-major padded
__device__ float g_WbT[TAPS * SIZE];       // tap-major: WbT[d][j] = W[j-BW+d][j]

// ---------------------------------------------------------------------------
// templated banded product (smem): compile-time widths -> no runtime division,
// constant address strides, unrollable inner loop.
// ---------------------------------------------------------------------------
template<int HA, int HB, int HD>
__device__ __forceinline__ void bprodT(const float* __restrict__ A,
                                       const float* __restrict__ B,
                                       float* __restrict__ D, int tid)
{
    constexpr int WA = 2 * HA + 1, WB = 2 * HB + 1, WD = 2 * HD + 1;
    #pragma unroll 1
    for (int e = tid; e < SIZE * WD; e += 1024) {
        int r = e / WD;                       // division by constant
        int o = e - r * WD;
        int c = r - HD + o;
        float s = 0.0f;
        if (c >= 0 && c < SIZE) {
            int klo = max(max(r - HA, c - HB), 0);
            int khi = min(min(r + HA, c + HB), SIZE - 1);
            const float* ap = A + r * WA + (klo - r + HA);
            const float* bp = B + klo * WB + (c - klo + HB);
            #pragma unroll 4
            for (int k = klo; k <= khi; k++) {
                s += (*ap) * (*bp);
                ap += 1;
                bp += (WB - 1);
            }
        }
        D[e] = s;
    }
}

// closed-form tridiagonal inverse entry (validated R11):
__device__ __forceinline__ float ginv(const float* co, const float* th,
                                      const float* ph, float invthn, int i, int j)
{
    float prod = 1.0f;
    if (i <= j) {
        for (int k = i; k < j; k++) prod *= co[k];
        return prod * th[i] * ph[j + 1] * invthn;
    } else {
        for (int k = j + 1; k <= i; k++) prod *= co[k];
        return prod * th[j] * ph[i + 1] * invthn;
    }
}

// ---------------------------------------------------------------------------
// K1: one CTA (mod 6) builds one complete 5-sweep chain band in smem.
// parts 0..3: X chains (store G^T; C = G0^T G1^T G2^T G3^T G4^T)
// parts 4..5: Y chains (store G;   C = G4 G3 G2 G1 G0)
// X chain p: X-order sweeps m=5p+q (k=m>>1, t=(k+(m&1))*DT, dt=DT/2)
// Y chain p: Y-order sweeps m=5(p-4)+q (t=m*DT+DT/2, dt=DT)
// ---------------------------------------------------------------------------
#define K1_CO   0
#define K1_TH   (K1_CO + 5 * SIZE)          // th[q*130+i] = theta_{i-1}
#define K1_PH   (K1_TH + 5 * 130)
#define K1_IV   (K1_PH + 5 * 130)           // 8 (5 used)
#define K1_G    (K1_IV + 8)                 // 5 * 128 * GW
#define K1_A1   (K1_G + 5 * SIZE * GW)      // 128*21
#define K1_A2   (K1_A1 + SIZE * WA1)
#define K1_A3   (K1_A2 + SIZE * WA1)        // 128*25
#define K1_C    (K1_A3 + SIZE * WC)
#define K1_TOT  (K1_C + SIZE * WC)

__global__ void __launch_bounds__(1024, 1)
chain_kernel(const float* __restrict__ abx, const float* __restrict__ atx,
             const float* __restrict__ aqx, const float* __restrict__ bby,
             const float* __restrict__ bty, const float* __restrict__ bqy)
{
    extern __shared__ float sh[];
    float* co  = sh + K1_CO;
    float* th  = sh + K1_TH;
    float* ph  = sh + K1_PH;
    float* ivt = sh + K1_IV;
    float* gbs = sh + K1_G;
    float* A1  = sh + K1_A1;
    float* A2  = sh + K1_A2;
    float* A3  = sh + K1_A3;
    float* C   = sh + K1_C;

    const int tid  = threadIdx.x;
    const int part = blockIdx.x % 6;
    const bool isY = part >= 4;

    // ---- coefficients (5 sweeps x 128, parallel) ----
    for (int e = tid; e < 5 * SIZE; e += 1024) {
        int q = e >> 7, i = e & 127;
        int m = isY ? (part - 4) * 5 + q : part * 5 + q;
        float t, dt; const float *bp, *lp, *qp;
        if (isY) { t = m * 0.01f + 0.005f;                   dt = 0.01f;  bp = bby; lp = bty; qp = bqy; }
        else     { int k = m >> 1; t = (k + (m & 1)) * 0.01f; dt = 0.005f; bp = abx; lp = atx; qp = aqx; }
        int im = max(i - 1, 0), ip = min(i + 1, 127);
        float vm = fmaxf(bp[im] + lp[im] * t + qp[im] * t * t, EPSF);
        float vc = fmaxf(bp[i]  + lp[i]  * t + qp[i]  * t * t, EPSF);
        float vp = fmaxf(bp[ip] + lp[ip] * t + qp[ip] * t * t, EPSF);
        co[q * SIZE + i] = (vm + vc + vp) * (1.0f / 3.0f) * dt;
    }
    __syncthreads();

    // ---- theta (warp0 lanes 0..4) / phi (warp1 lanes 0..4) ----
    if (tid < 5) {
        const int q = tid;
        const float* c = &co[q * SIZE];
        float t2 = 1.0f, cprev = c[0];
        float t1 = 1.0f + cprev;
        th[q * 130 + 0] = 1.0f; th[q * 130 + 1] = t1;
        for (int r = 1; r < SIZE; r++) {
            float cr = c[r];
            float br = (r == SIZE - 1) ? (1.0f + cr) : (1.0f + 2.0f * cr);
            float tn = br * t1 - (cr * cprev) * t2;
            th[q * 130 + r + 1] = tn;
            t2 = t1; t1 = tn; cprev = cr;
        }
        ivt[q] = 1.0f / th[q * 130 + SIZE];
    } else if (tid >= 32 && tid < 37) {
        const int q = tid - 32;
        const float* c = &co[q * SIZE];
        float p2 = 1.0f, cnext = c[SIZE - 1];
        float p1 = 1.0f + cnext;
        ph[q * 130 + SIZE] = 1.0f; ph[q * 130 + SIZE - 1] = p1;
        for (int r = SIZE - 2; r >= 0; r--) {
            float cr = c[r];
            float br = (r == 0) ? (1.0f + cr) : (1.0f + 2.0f * cr);
            float pn = br * p1 - (cr * cnext) * p2;
            ph[q * 130 + r] = pn;
            p2 = p1; p1 = pn; cnext = cr;
        }
    }
    __syncthreads();

    // ---- G bands (hw 5). X parts store G^T (swap args) ----
    for (int e = tid; e < 5 * SIZE * GW; e += 1024) {
        int q = e / (SIZE * GW);
        int rem = e - q * (SIZE * GW);
        int r = rem / GW, o = rem - r * GW;
        int c = r - SBW + o;
        float v = 0.0f;
        if (c >= 0 && c < SIZE) {
            const float* cq = &co[q * SIZE];
            const float* tq = &th[q * 130];
            const float* pq = &ph[q * 130];
            v = isY ? ginv(cq, tq, pq, ivt[q], r, c)
                    : ginv(cq, tq, pq, ivt[q], c, r);
        }
        gbs[e] = v;
    }
    __syncthreads();

    // ---- product tree in smem (templated widths) ----
    const float* g0 = gbs + (isY ? 4 : 0) * SIZE * GW;
    const float* g1 = gbs + (isY ? 3 : 1) * SIZE * GW;
    const float* g2 = gbs + 2 * SIZE * GW;
    const float* g3 = gbs + (isY ? 1 : 3) * SIZE * GW;
    const float* g4 = gbs + (isY ? 0 : 4) * SIZE * GW;

    bprodT<SBW, SBW, HA1>(g0, g1, A1, tid);
    bprodT<SBW, SBW, HA1>(g2, g3, A2, tid);
    __syncthreads();
    bprodT<HA1, HA1, HC>(A1, A2, A3, tid);
    __syncthreads();
    bprodT<HC, SBW, HC>(A3, g4, C, tid);
    __syncthreads();

    for (int e = tid; e < SIZE * WC; e += 1024)
        g_cb[part][e] = C[e];
}

// ---------------------------------------------------------------------------
// K2: finalize band tables. CTA (mod 2):
// role 0: E1=C0*C1, E2=C2*C3 (hw 12), then WbT[d][j] = (E1*E2)[j-4+d][j]
// role 1: Lb[i][d] = (C5*C4)[i][i-4+d]
// ---------------------------------------------------------------------------
__global__ void __launch_bounds__(1024, 1)
finalize_kernel()
{
    extern __shared__ float sh[];
    float* cs = sh;                     // up to 4 * 3200
    float* E  = sh + 4 * SIZE * WC;     // 2 * 3200
    const int tid  = threadIdx.x;
    const int role = blockIdx.x % 2;

    if (role == 0) {
        for (int m = tid; m < 4 * SIZE * WC; m += 1024)
            cs[m] = ((const float*)g_cb)[m];                 // C0..C3
        __syncthreads();

        bprodT<HC, HC, HC>(cs,                 cs + SIZE * WC,     E,            tid);
        bprodT<HC, HC, HC>(cs + 2 * SIZE * WC, cs + 3 * SIZE * WC, E + SIZE * WC, tid);
        __syncthreads();

        // WbT[d][j] = (E1*E2)[j-4+d][j]
        const float* E1 = E, *E2 = E + SIZE * WC;
        for (int e = tid; e < TAPS * SIZE; e += 1024) {
            int d = e / SIZE, j = e - d * SIZE;
            int r = j - BW + d;
            float s = 0.0f;
            if (r >= 0 && r < SIZE) {
                int klo = max(max(r, j) - HC, 0), khi = min(min(r, j) + HC, SIZE - 1);
                for (int k = klo; k <= khi; k++)
                    s += E1[r * WC + (k - r + HC)] * E2[k * WC + (j - k + HC)];
            }
            g_WbT[e] = s;
        }
    } else {
        for (int m = tid; m < 2 * SIZE * WC; m += 1024)
            cs[m] = ((const float*)g_cb)[4 * SIZE * WC + m]; // C4, C5
        __syncthreads();

        const float* C4 = cs, *C5 = cs + SIZE * WC;
        for (int e = tid; e < SIZE * TAPS; e += 1024) {
            int i = e / TAPS, d = e - i * TAPS;
            int c = i - BW + d;
            float s = 0.0f;
            if (c >= 0 && c < SIZE) {
                int klo = max(max(i, c) - HC, 0), khi = min(min(i, c) + HC, SIZE - 1);
                for (int k = klo; k <= khi; k++)
                    s += C5[i * WC + (k - i + HC)] * C4[k * WC + (c - k + HC)];
            }
            g_Lb[i * CW + d] = s;
        }
    }
}

// ---------------------------------------------------------------------------
// band_kernel: R12 structure, occupancy 2 -> 3 (register cap 84 via launch
// bounds; spread model predicts negligible oe3 contention at T_CTA~26K).
// ONE CTA per image, 256 threads, 8 warps x 16 rows. Register sliding window
// (9 float4), Lb warp-uniform LDG, Wb in 36 regs (tap-major).
// ---------------------------------------------------------------------------
__device__ __forceinline__ float4 f4fma(float c, float4 w, float4 a) {
    a.x = fmaf(c, w.x, a.x); a.y = fmaf(c, w.y, a.y);
    a.z = fmaf(c, w.z, a.z); a.w = fmaf(c, w.w, a.w);
    return a;
}

__global__ void __launch_bounds__(256, 3)
band_kernel(const float* __restrict__ uin, float* __restrict__ uout)
{
    extern __shared__ float us[];            // 128*128 floats = 64KB

    const int tid  = threadIdx.x, w = tid >> 5, lane = tid & 31;
    const size_t off = (size_t)blockIdx.x * (SIZE * SIZE);
    const float* src = uin + off;

    const float4* src4 = (const float4*)src;
    #pragma unroll
    for (int q = 0; q < 16; q++) {
        int m = tid + q * 256;
        int r = m >> 5, c4 = (m & 31) * 4;
        *(float4*)&us[r * SIZE + c4] = src4[m];
    }

    float4 wb4[TAPS];
    #pragma unroll
    for (int d = 0; d < TAPS; d++)
        wb4[d] = *(const float4*)&g_WbT[d * SIZE + 4 * lane];
    __syncthreads();

    const int il0 = w * 16;
    float4 win[TAPS];
    #pragma unroll
    for (int t = 0; t < TAPS - 1; t++) {
        int r = max(il0 - BW + t, 0);        // clamp: edge coeffs are zero
        win[t] = *(const float4*)&us[r * SIZE + 4 * lane];
    }

    float* dst = uout + off;
    #pragma unroll
    for (int rr = 0; rr < 16; rr++) {
        int rn = min(il0 + rr + BW, SIZE - 1);
        win[(rr + TAPS - 1) % TAPS] = *(const float4*)&us[rn * SIZE + 4 * lane];
        const int gi = il0 + rr;

        const float* cr = &g_Lb[gi * CW];
        float4 c0 = *(const float4*)cr;
        float4 c1 = *(const float4*)(cr + 4);
        float  c8 = cr[8];
        float4 t4 = make_float4(0.f, 0.f, 0.f, 0.f);
        t4 = f4fma(c0.x, win[(rr + 0) % TAPS], t4);
        t4 = f4fma(c0.y, win[(rr + 1) % TAPS], t4);
        t4 = f4fma(c0.z, win[(rr + 2) % TAPS], t4);
        t4 = f4fma(c0.w, win[(rr + 3) % TAPS], t4);
        t4 = f4fma(c1.x, win[(rr + 4) % TAPS], t4);
        t4 = f4fma(c1.y, win[(rr + 5) % TAPS], t4);
        t4 = f4fma(c1.z, win[(rr + 6) % TAPS], t4);
        t4 = f4fma(c1.w, win[(rr + 7) % TAPS], t4);
        t4 = f4fma(c8,   win[(rr + 8) % TAPS], t4);

        float Tl[12];
        Tl[0] = __shfl_up_sync(0xffffffffu, t4.x, 1);
        Tl[1] = __shfl_up_sync(0xffffffffu, t4.y, 1);
        Tl[2] = __shfl_up_sync(0xffffffffu, t4.z, 1);
        Tl[3] = __shfl_up_sync(0xffffffffu, t4.w, 1);
        Tl[4] = t4.x; Tl[5] = t4.y; Tl[6] = t4.z; Tl[7] = t4.w;
        Tl[8]  = __shfl_down_sync(0xffffffffu, t4.x, 1);
        Tl[9]  = __shfl_down_sync(0xffffffffu, t4.y, 1);
        Tl[10] = __shfl_down_sync(0xffffffffu, t4.z, 1);
        Tl[11] = __shfl_down_sync(0xffffffffu, t4.w, 1);

        float4 o = make_float4(0.f, 0.f, 0.f, 0.f);
        #pragma unroll
        for (int d = 0; d < TAPS; d++) {
            o.x = fmaf(wb4[d].x, Tl[0 + d], o.x);
            o.y = fmaf(wb4[d].y, Tl[1 + d], o.y);
            o.z = fmaf(wb4[d].z, Tl[2 + d], o.z);
            o.w = fmaf(wb4[d].w, Tl[3 + d], o.w);
        }
        *(float4*)&dst[gi * SIZE + 4 * lane] = o;
    }
}

// ---------------------------------------------------------------------------
extern "C" void kernel_launch(void* const* d_in, const int* in_sizes, int n_in,
                              void* d_out, int out_size)
{
    const float* u   = (const float*)d_in[0];
    const float* abx = (const float*)d_in[1];
    const float* bby = (const float*)d_in[4];
    const float* atx = (const float*)d_in[5];
    const float* bty = (const float*)d_in[8];
    const float* aqx = (const float*)d_in[9];
    const float* bqy = (const float*)d_in[12];
    float* out = (float*)d_out;

    const int smem_k1   = K1_TOT * (int)sizeof(float);            // ~83 KB
    const int smem_k2   = 6 * SIZE * WC * (int)sizeof(float);     // 76.8 KB
    const int smem_band = SIZE * SIZE * (int)sizeof(float);       // 65536

    cudaFuncSetAttribute(chain_kernel,    cudaFuncAttributeMaxDynamicSharedMemorySize, smem_k1);
    cudaFuncSetAttribute(finalize_kernel, cudaFuncAttributeMaxDynamicSharedMemorySize, smem_k2);
    cudaFuncSetAttribute(band_kernel,     cudaFuncAttributeMaxDynamicSharedMemorySize, smem_band);

    const int batch = out_size / (SIZE * SIZE);   // 2048

    chain_kernel<<<150, 1024, smem_k1>>>(abx, atx, aqx, bby, bty, bqy);
    finalize_kernel<<<148, 1024, smem_k2>>>();
    band_kernel<<<batch, 256, smem_band>>>(u, out);
}

// round 17
// speedup vs baseline: 1.1485x; 1.1485x over previous
#include <cuda_runtime.h>
#include <cstdint>

#define SIZE   128
#define EPSF   1e-6f
#define BW     4            // final operator half bandwidth
#define TAPS   9            // 2*BW+1
#define CW     12           // padded Lb coeff row width
#define SBW    5            // single-sweep inverse half-width
#define GW     11           // 2*SBW+1
#define HA1    10           // A1/A2 half-width (exact)
#define WA1    21
#define HC     12           // chain / E half-width (cap, validated)
#define WC     25

// ---------------------------------------------------------------------------
// Globals
// ---------------------------------------------------------------------------
// chains 0..3 = X chains (W = C0*C1*C2*C3), 4..5 = Y chains (L = C5*C4)
__device__ float g_cb[6][SIZE * WC];
__device__ float g_Lb[SIZE * CW];          // row-major padded
__device__ float g_WbT[TAPS * SIZE];       // tap-major: WbT[d][j] = W[j-BW+d][j]

// ---------------------------------------------------------------------------
// Zero-padded band product. Step 1: pad B (band hw HB, width 2HB+1) into
// Bp with HA extra zero rows on each side and column window 2(HD+HA)+1
// (zero outside the true band). Step 2: branch-free product
//   D[r][o] = sum_{d=0..2HA} A[r][d] * Bp[(r+d)][(o + 2HA - d)]
// (A stores 0 for out-of-range columns, so no clamping is needed anywhere).
// ---------------------------------------------------------------------------
template<int HA, int HB, int HD>
__device__ __forceinline__ void padB(const float* __restrict__ B,
                                     float* __restrict__ Bp, int tid)
{
    constexpr int WB  = 2 * HB + 1;
    constexpr int WBP = 2 * (HD + HA) + 1;
    constexpr int RP  = SIZE + 2 * HA;
    #pragma unroll 1
    for (int e = tid; e < RP * WBP; e += 1024) {
        int kp  = e / WBP;                 // div by constant
        int col = e - kp * WBP;
        int k   = kp - HA;
        int ck  = col - (HD + HA);         // c - k
        float v = 0.0f;
        if (k >= 0 && k < SIZE && ck >= -HB && ck <= HB)
            v = B[k * WB + ck + HB];
        Bp[e] = v;
    }
}

template<int HA, int HB, int HD>
__device__ __forceinline__ void prodPad(const float* __restrict__ A,
                                        const float* __restrict__ Bp,
                                        float* __restrict__ D, int tid)
{
    constexpr int WA  = 2 * HA + 1;
    constexpr int WD  = 2 * HD + 1;
    constexpr int WBP = 2 * (HD + HA) + 1;
    const int r   = tid >> 3;              // 8 threads per row
    const int sub = tid & 7;

    float Areg[WA];
    #pragma unroll
    for (int d = 0; d < WA; d++) Areg[d] = A[r * WA + d];   // warp-broadcast LDS

    #pragma unroll 1
    for (int o = sub; o < WD; o += 8) {
        int c = r - HD + o;
        float s = 0.0f;
        if (c >= 0 && c < SIZE) {
            const float* bp = &Bp[r * WBP + o + 2 * HA];     // d=0 term
            #pragma unroll
            for (int d = 0; d < WA; d++)
                s += Areg[d] * bp[d * (WBP - 1)];
        }
        D[r * WD + o] = s;
    }
}

// closed-form tridiagonal inverse entry (validated R11):
__device__ __forceinline__ float ginv(const float* co, const float* th,
                                      const float* ph, float invthn, int i, int j)
{
    float prod = 1.0f;
    if (i <= j) {
        for (int k = i; k < j; k++) prod *= co[k];
        return prod * th[i] * ph[j + 1] * invthn;
    } else {
        for (int k = j + 1; k <= i; k++) prod *= co[k];
        return prod * th[j] * ph[i + 1] * invthn;
    }
}

// ---------------------------------------------------------------------------
// K1: one CTA (mod 6) builds one complete 5-sweep chain band in smem.
// parts 0..3: X chains (store G^T; C = G0^T G1^T G2^T G3^T G4^T)
// parts 4..5: Y chains (store G;   C = G4 G3 G2 G1 G0)
// ---------------------------------------------------------------------------
#define K1_CO   0
#define K1_TH   (K1_CO + 5 * SIZE)
#define K1_PH   (K1_TH + 5 * 130)
#define K1_IV   (K1_PH + 5 * 130)
#define K1_G    (K1_IV + 8)                 // 5 * 128 * GW
#define K1_A1   (K1_G + 5 * SIZE * GW)      // 128*21
#define K1_A2   (K1_A1 + SIZE * WA1)
#define K1_A3   (K1_A2 + SIZE * WA1)        // 128*25
#define K1_C    (K1_A3 + SIZE * WC)
#define K1_PAD  (K1_C + SIZE * WC)          // scratch: max 152*49 = 7448
#define K1_TOT  (K1_PAD + 7448)

__global__ void __launch_bounds__(1024, 1)
chain_kernel(const float* __restrict__ abx, const float* __restrict__ atx,
             const float* __restrict__ aqx, const float* __restrict__ bby,
             const float* __restrict__ bty, const float* __restrict__ bqy)
{
    extern __shared__ float sh[];
    float* co  = sh + K1_CO;
    float* th  = sh + K1_TH;
    float* ph  = sh + K1_PH;
    float* ivt = sh + K1_IV;
    float* gbs = sh + K1_G;
    float* A1  = sh + K1_A1;
    float* A2  = sh + K1_A2;
    float* A3  = sh + K1_A3;
    float* C   = sh + K1_C;
    float* PAD = sh + K1_PAD;

    const int tid  = threadIdx.x;
    const int part = blockIdx.x % 6;
    const bool isY = part >= 4;

    // ---- coefficients (5 sweeps x 128, parallel) ----
    for (int e = tid; e < 5 * SIZE; e += 1024) {
        int q = e >> 7, i = e & 127;
        int m = isY ? (part - 4) * 5 + q : part * 5 + q;
        float t, dt; const float *bp, *lp, *qp;
        if (isY) { t = m * 0.01f + 0.005f;                   dt = 0.01f;  bp = bby; lp = bty; qp = bqy; }
        else     { int k = m >> 1; t = (k + (m & 1)) * 0.01f; dt = 0.005f; bp = abx; lp = atx; qp = aqx; }
        int im = max(i - 1, 0), ip = min(i + 1, 127);
        float vm = fmaxf(bp[im] + lp[im] * t + qp[im] * t * t, EPSF);
        float vc = fmaxf(bp[i]  + lp[i]  * t + qp[i]  * t * t, EPSF);
        float vp = fmaxf(bp[ip] + lp[ip] * t + qp[ip] * t * t, EPSF);
        co[q * SIZE + i] = (vm + vc + vp) * (1.0f / 3.0f) * dt;
    }
    __syncthreads();

    // ---- theta (warp0 lanes 0..4) / phi (warp1 lanes 0..4) ----
    if (tid < 5) {
        const int q = tid;
        const float* c = &co[q * SIZE];
        float t2 = 1.0f, cprev = c[0];
        float t1 = 1.0f + cprev;
        th[q * 130 + 0] = 1.0f; th[q * 130 + 1] = t1;
        for (int r = 1; r < SIZE; r++) {
            float cr = c[r];
            float br = (r == SIZE - 1) ? (1.0f + cr) : (1.0f + 2.0f * cr);
            float tn = br * t1 - (cr * cprev) * t2;
            th[q * 130 + r + 1] = tn;
            t2 = t1; t1 = tn; cprev = cr;
        }
        ivt[q] = 1.0f / th[q * 130 + SIZE];
    } else if (tid >= 32 && tid < 37) {
        const int q = tid - 32;
        const float* c = &co[q * SIZE];
        float p2 = 1.0f, cnext = c[SIZE - 1];
        float p1 = 1.0f + cnext;
        ph[q * 130 + SIZE] = 1.0f; ph[q * 130 + SIZE - 1] = p1;
        for (int r = SIZE - 2; r >= 0; r--) {
            float cr = c[r];
            float br = (r == 0) ? (1.0f + cr) : (1.0f + 2.0f * cr);
            float pn = br * p1 - (cr * cnext) * p2;
            ph[q * 130 + r] = pn;
            p2 = p1; p1 = pn; cnext = cr;
        }
    }
    __syncthreads();

    // ---- G bands (hw 5). X parts store G^T (swap args) ----
    for (int e = tid; e < 5 * SIZE * GW; e += 1024) {
        int q = e / (SIZE * GW);
        int rem = e - q * (SIZE * GW);
        int r = rem / GW, o = rem - r * GW;
        int c = r - SBW + o;
        float v = 0.0f;
        if (c >= 0 && c < SIZE) {
            const float* cq = &co[q * SIZE];
            const float* tq = &th[q * 130];
            const float* pq = &ph[q * 130];
            v = isY ? ginv(cq, tq, pq, ivt[q], r, c)
                    : ginv(cq, tq, pq, ivt[q], c, r);
        }
        gbs[e] = v;
    }
    __syncthreads();

    // ---- product tree with zero-padded branch-free products ----
    const float* g0 = gbs + (isY ? 4 : 0) * SIZE * GW;
    const float* g1 = gbs + (isY ? 3 : 1) * SIZE * GW;
    const float* g2 = gbs + 2 * SIZE * GW;
    const float* g3 = gbs + (isY ? 1 : 3) * SIZE * GW;
    const float* g4 = gbs + (isY ? 0 : 4) * SIZE * GW;

    padB<SBW, SBW, HA1>(g1, PAD, tid);  __syncthreads();
    prodPad<SBW, SBW, HA1>(g0, PAD, A1, tid);  __syncthreads();

    padB<SBW, SBW, HA1>(g3, PAD, tid);  __syncthreads();
    prodPad<SBW, SBW, HA1>(g2, PAD, A2, tid);  __syncthreads();

    padB<HA1, HA1, HC>(A2, PAD, tid);  __syncthreads();
    prodPad<HA1, HA1, HC>(A1, PAD, A3, tid);  __syncthreads();

    padB<HC, SBW, HC>(g4, PAD, tid);  __syncthreads();
    prodPad<HC, SBW, HC>(A3, PAD, C, tid);  __syncthreads();

    for (int e = tid; e < SIZE * WC; e += 1024)
        g_cb[part][e] = C[e];
}

// ---------------------------------------------------------------------------
// K2: finalize band tables. CTA (mod 2):
// role 0: E1=C0*C1, E2=C2*C3 (hw 12), then WbT[d][j] = (E1*E2)[j-4+d][j]
// role 1: Lb[i][d] = (C5*C4)[i][i-4+d]
// ---------------------------------------------------------------------------
#define K2_CS   0
#define K2_E    (K2_CS + 4 * SIZE * WC)
#define K2_PAD  (K2_E + 2 * SIZE * WC)       // 152*49 = 7448
#define K2_TOT  (K2_PAD + 7448)

__global__ void __launch_bounds__(1024, 1)
finalize_kernel()
{
    extern __shared__ float sh[];
    float* cs  = sh + K2_CS;
    float* E   = sh + K2_E;
    float* PAD = sh + K2_PAD;
    const int tid  = threadIdx.x;
    const int role = blockIdx.x % 2;

    if (role == 0) {
        for (int m = tid; m < 4 * SIZE * WC; m += 1024)
            cs[m] = ((const float*)g_cb)[m];                 // C0..C3
        __syncthreads();

        padB<HC, HC, HC>(cs + SIZE * WC, PAD, tid);  __syncthreads();
        prodPad<HC, HC, HC>(cs, PAD, E, tid);  __syncthreads();

        padB<HC, HC, HC>(cs + 3 * SIZE * WC, PAD, tid);  __syncthreads();
        prodPad<HC, HC, HC>(cs + 2 * SIZE * WC, PAD, E + SIZE * WC, tid);  __syncthreads();

        // WbT[d][j] = (E1*E2)[j-4+d][j]
        const float* E1 = E, *E2 = E + SIZE * WC;
        for (int e = tid; e < TAPS * SIZE; e += 1024) {
            int d = e / SIZE, j = e - d * SIZE;
            int r = j - BW + d;
            float s = 0.0f;
            if (r >= 0 && r < SIZE) {
                int klo = max(max(r, j) - HC, 0), khi = min(min(r, j) + HC, SIZE - 1);
                for (int k = klo; k <= khi; k++)
                    s += E1[r * WC + (k - r + HC)] * E2[k * WC + (j - k + HC)];
            }
            g_WbT[e] = s;
        }
    } else {
        for (int m = tid; m < 2 * SIZE * WC; m += 1024)
            cs[m] = ((const float*)g_cb)[4 * SIZE * WC + m]; // C4, C5
        __syncthreads();

        const float* C4 = cs, *C5 = cs + SIZE * WC;
        for (int e = tid; e < SIZE * TAPS; e += 1024) {
            int i = e / TAPS, d = e - i * TAPS;
            int c = i - BW + d;
            float s = 0.0f;
            if (c >= 0 && c < SIZE) {
                int klo = max(max(i, c) - HC, 0), khi = min(min(i, c) + HC, SIZE - 1);
                for (int k = klo; k <= khi; k++)
                    s += C5[i * WC + (k - i + HC)] * C4[k * WC + (c - k + HC)];
            }
            g_Lb[i * CW + d] = s;
        }
    }
}

// ---------------------------------------------------------------------------
// band_kernel (R12/R15 verbatim — measured 52.9us, occ 2): ONE CTA per image,
// 256 threads, 8 warps x 16 rows. Register sliding window (9 float4),
// Lb warp-uniform LDG, Wb in 36 regs (tap-major).
// ---------------------------------------------------------------------------
__device__ __forceinline__ float4 f4fma(float c, float4 w, float4 a) {
    a.x = fmaf(c, w.x, a.x); a.y = fmaf(c, w.y, a.y);
    a.z = fmaf(c, w.z, a.z); a.w = fmaf(c, w.w, a.w);
    return a;
}

__global__ void __launch_bounds__(256, 2)
band_kernel(const float* __restrict__ uin, float* __restrict__ uout)
{
    extern __shared__ float us[];            // 128*128 floats = 64KB

    const int tid  = threadIdx.x, w = tid >> 5, lane = tid & 31;
    const size_t off = (size_t)blockIdx.x * (SIZE * SIZE);
    const float* src = uin + off;

    const float4* src4 = (const float4*)src;
    #pragma unroll
    for (int q = 0; q < 16; q++) {
        int m = tid + q * 256;
        int r = m >> 5, c4 = (m & 31) * 4;
        *(float4*)&us[r * SIZE + c4] = src4[m];
    }

    float4 wb4[TAPS];
    #pragma unroll
    for (int d = 0; d < TAPS; d++)
        wb4[d] = *(const float4*)&g_WbT[d * SIZE + 4 * lane];
    __syncthreads();

    const int il0 = w * 16;
    float4 win[TAPS];
    #pragma unroll
    for (int t = 0; t < TAPS - 1; t++) {
        int r = max(il0 - BW + t, 0);        // clamp: edge coeffs are zero
        win[t] = *(const float4*)&us[r * SIZE + 4 * lane];
    }

    float* dst = uout + off;
    #pragma unroll
    for (int rr = 0; rr < 16; rr++) {
        int rn = min(il0 + rr + BW, SIZE - 1);
        win[(rr + TAPS - 1) % TAPS] = *(const float4*)&us[rn * SIZE + 4 * lane];
        const int gi = il0 + rr;

        const float* cr = &g_Lb[gi * CW];
        float4 c0 = *(const float4*)cr;
        float4 c1 = *(const float4*)(cr + 4);
        float  c8 = cr[8];
        float4 t4 = make_float4(0.f, 0.f, 0.f, 0.f);
        t4 = f4fma(c0.x, win[(rr + 0) % TAPS], t4);
        t4 = f4fma(c0.y, win[(rr + 1) % TAPS], t4);
        t4 = f4fma(c0.z, win[(rr + 2) % TAPS], t4);
        t4 = f4fma(c0.w, win[(rr + 3) % TAPS], t4);
        t4 = f4fma(c1.x, win[(rr + 4) % TAPS], t4);
        t4 = f4fma(c1.y, win[(rr + 5) % TAPS], t4);
        t4 = f4fma(c1.z, win[(rr + 6) % TAPS], t4);
        t4 = f4fma(c1.w, win[(rr + 7) % TAPS], t4);
        t4 = f4fma(c8,   win[(rr + 8) % TAPS], t4);

        float Tl[12];
        Tl[0] = __shfl_up_sync(0xffffffffu, t4.x, 1);
        Tl[1] = __shfl_up_sync(0xffffffffu, t4.y, 1);
        Tl[2] = __shfl_up_sync(0xffffffffu, t4.z, 1);
        Tl[3] = __shfl_up_sync(0xffffffffu, t4.w, 1);
        Tl[4] = t4.x; Tl[5] = t4.y; Tl[6] = t4.z; Tl[7] = t4.w;
        Tl[8]  = __shfl_down_sync(0xffffffffu, t4.x, 1);
        Tl[9]  = __shfl_down_sync(0xffffffffu, t4.y, 1);
        Tl[10] = __shfl_down_sync(0xffffffffu, t4.z, 1);
        Tl[11] = __shfl_down_sync(0xffffffffu, t4.w, 1);

        float4 o = make_float4(0.f, 0.f, 0.f, 0.f);
        #pragma unroll
        for (int d = 0; d < TAPS; d++) {
            o.x = fmaf(wb4[d].x, Tl[0 + d], o.x);
            o.y = fmaf(wb4[d].y, Tl[1 + d], o.y);
            o.z = fmaf(wb4[d].z, Tl[2 + d], o.z);
            o.w = fmaf(wb4[d].w, Tl[3 + d], o.w);
        }
        *(float4*)&dst[gi * SIZE + 4 * lane] = o;
    }
}

// ---------------------------------------------------------------------------
extern "C" void kernel_launch(void* const* d_in, const int* in_sizes, int n_in,
                              void* d_out, int out_size)
{
    const float* u   = (const float*)d_in[0];
    const float* abx = (const float*)d_in[1];
    const float* bby = (const float*)d_in[4];
    const float* atx = (const float*)d_in[5];
    const float* bty = (const float*)d_in[8];
    const float* aqx = (const float*)d_in[9];
    const float* bqy = (const float*)d_in[12];
    float* out = (float*)d_out;

    const int smem_k1   = K1_TOT * (int)sizeof(float);            // ~113 KB
    const int smem_k2   = K2_TOT * (int)sizeof(float);            // ~107 KB
    const int smem_band = SIZE * SIZE * (int)sizeof(float);       // 65536

    cudaFuncSetAttribute(chain_kernel,    cudaFuncAttributeMaxDynamicSharedMemorySize, smem_k1);
    cudaFuncSetAttribute(finalize_kernel, cudaFuncAttributeMaxDynamicSharedMemorySize, smem_k2);
    cudaFuncSetAttribute(band_kernel,     cudaFuncAttributeMaxDynamicSharedMemorySize, smem_band);

    const int batch = out_size / (SIZE * SIZE);   // 2048

    chain_kernel<<<150, 1024, smem_k1>>>(abx, atx, aqx, bby, bty, bqy);
    finalize_kernel<<<148, 1024, smem_k2>>>();
    band_kernel<<<batch, 256, smem_band>>>(u, out);
}